// round 13
// baseline (speedup 1.0000x reference)
#include <cuda_runtime.h>

// Loss_46883863003176: out = sum((pred - tgt)^2) / S / B
// pred, tgt: (4096, 2047, 2) float32, contiguous. Pure HBM-bound reduction.
//
// Base: R7 winner (1184 = 148x8 blocks x 256 threads, grid-stride, __ldcs,
// pre-scaled atomicAdd epilogue, wraparound last-block publish). Change under
// test: 8 independent LDG.128 in flight per thread (unroll-4), expressed via
// pragma-unrolled batch arrays. Single launch, no memset, no allocations.

#define BLOCK_THREADS 256
#define NUM_BLOCKS    (148 * 8)   // 1184 CTAs, 8/SM, 64 warps/SM
#define UNROLL        4

__device__ float        g_accum   = 0.0f;  // reset by winning block each launch
__device__ unsigned int g_arrival = 0;     // wraps to 0 every NUM_BLOCKS arrivals

__global__ void __launch_bounds__(BLOCK_THREADS)
mse_fused_kernel(const float4* __restrict__ pred,
                 const float4* __restrict__ tgt,
                 float* __restrict__ out,
                 int n_vec4,          // number of float4 elements
                 float inv_norm)      // 1 / (S * B)
{
    const int tid     = threadIdx.x;
    const int gthread = blockIdx.x * BLOCK_THREADS + tid;
    const int stride  = gridDim.x * BLOCK_THREADS;   // 303,104

    float acc = 0.0f;

    int i = gthread;
    // Main loop: UNROLL independent (pred, tgt) float4 pairs per iteration.
    // __ldcs: streaming (evict-first) — data is touch-once.
    for (; i + (UNROLL - 1) * stride < n_vec4; i += UNROLL * stride) {
        float4 pv[UNROLL];
        float4 tv[UNROLL];
        #pragma unroll
        for (int j = 0; j < UNROLL; j++)
            pv[j] = __ldcs(&pred[i + j * stride]);
        #pragma unroll
        for (int j = 0; j < UNROLL; j++)
            tv[j] = __ldcs(&tgt[i + j * stride]);

        #pragma unroll
        for (int j = 0; j < UNROLL; j++) {
            float dx = pv[j].x - tv[j].x;
            float dy = pv[j].y - tv[j].y;
            float dz = pv[j].z - tv[j].z;
            float dw = pv[j].w - tv[j].w;
            acc = fmaf(dx, dx, acc);
            acc = fmaf(dy, dy, acc);
            acc = fmaf(dz, dz, acc);
            acc = fmaf(dw, dw, acc);
        }
    }
    // Tail: up to UNROLL-1 vectors per thread.
    for (; i < n_vec4; i += stride) {
        float4 p = __ldcs(&pred[i]);
        float4 t = __ldcs(&tgt[i]);
        float dx = p.x - t.x;
        float dy = p.y - t.y;
        float dz = p.z - t.z;
        float dw = p.w - t.w;
        acc = fmaf(dx, dx, acc);
        acc = fmaf(dy, dy, acc);
        acc = fmaf(dz, dz, acc);
        acc = fmaf(dw, dw, acc);
    }

    // Warp reduce
    #pragma unroll
    for (int off = 16; off > 0; off >>= 1)
        acc += __shfl_xor_sync(0xFFFFFFFFu, acc, off);

    // Block reduce via shared
    __shared__ float warp_sums[BLOCK_THREADS / 32];
    __shared__ bool  is_last;
    const int lane = tid & 31;
    const int wid  = tid >> 5;
    if (lane == 0) warp_sums[wid] = acc;
    __syncthreads();

    if (tid == 0) {
        float v = 0.0f;
        #pragma unroll
        for (int w = 0; w < BLOCK_THREADS / 32; w++)
            v += warp_sums[w];

        // Pre-scale so the final value needs no further math.
        atomicAdd(&g_accum, v * inv_norm);
        __threadfence();   // order the add before the arrival increment
        // atomicInc wraps to 0 at NUM_BLOCKS-1 -> self-resets each launch,
        // keeping graph replays deterministic.
        unsigned int prev = atomicInc(&g_arrival, NUM_BLOCKS - 1);
        is_last = (prev == NUM_BLOCKS - 1);
    }
    __syncthreads();

    // Last block: publish result, reset accumulator for the next replay.
    if (is_last && tid == 0) {
        float total = atomicAdd(&g_accum, 0.0f);   // atomic read
        out[0] = total;                             // overwrite poisoned d_out
        __threadfence();
        atomicExch(&g_accum, 0.0f);                 // reset for next launch
    }
}

extern "C" void kernel_launch(void* const* d_in, const int* in_sizes, int n_in,
                              void* d_out, int out_size)
{
    const float* pred = (const float*)d_in[0];
    const float* tgt  = (const float*)d_in[1];
    float* out = (float*)d_out;

    const long long total = (long long)in_sizes[0];   // B * S * 2 = 16,769,024
    const int n_vec4 = (int)(total / 4);              // 4,192,256
    // normalizer: S * B = total / 2
    const float inv_norm = 2.0f / (float)total;

    mse_fused_kernel<<<NUM_BLOCKS, BLOCK_THREADS>>>(
        (const float4*)pred, (const float4*)tgt, out, n_vec4, inv_norm);
}

// round 15
// speedup vs baseline: 1.1509x; 1.1509x over previous
#include <cuda_runtime.h>

// Loss_46883863003176: out = sum((pred - tgt)^2) / S / B
// pred, tgt: (4096, 2047, 2) float32, contiguous. Pure HBM-bound reduction.
//
// R7 winner structure (1184 = 148x8 blocks x 256 threads, grid-stride,
// unroll-2 = 4 in-flight LDG.128/thread, pre-scaled atomicAdd epilogue with
// wraparound last-block publish). Single controlled change vs R7: __ldcs
// (evict-first) -> __ldg (default NC cached) to preserve L2 sector
// coalescing. Single launch, no memset, no allocations, graph-capturable.

#define BLOCK_THREADS 256
#define NUM_BLOCKS    (148 * 8)   // 1184 CTAs, 8/SM, 64 warps/SM

__device__ float        g_accum   = 0.0f;  // reset by winning block each launch
__device__ unsigned int g_arrival = 0;     // wraps to 0 every NUM_BLOCKS arrivals

__global__ void __launch_bounds__(BLOCK_THREADS)
mse_fused_kernel(const float4* __restrict__ pred,
                 const float4* __restrict__ tgt,
                 float* __restrict__ out,
                 int n_vec4,          // number of float4 elements
                 float inv_norm)      // 1 / (S * B)
{
    const int tid     = threadIdx.x;
    const int gthread = blockIdx.x * BLOCK_THREADS + tid;
    const int stride  = gridDim.x * BLOCK_THREADS;   // 303,104

    float acc = 0.0f;

    // Unroll-by-2 grid-stride: 4 independent LDG.128 in flight per iteration
    // (measured sweet spot; deeper unroll regresses).
    int i = gthread;
    for (; i + stride < n_vec4; i += 2 * stride) {
        float4 p0 = __ldg(&pred[i]);
        float4 t0 = __ldg(&tgt[i]);
        float4 p1 = __ldg(&pred[i + stride]);
        float4 t1 = __ldg(&tgt[i + stride]);

        float d;
        d = p0.x - t0.x; acc = fmaf(d, d, acc);
        d = p0.y - t0.y; acc = fmaf(d, d, acc);
        d = p0.z - t0.z; acc = fmaf(d, d, acc);
        d = p0.w - t0.w; acc = fmaf(d, d, acc);
        d = p1.x - t1.x; acc = fmaf(d, d, acc);
        d = p1.y - t1.y; acc = fmaf(d, d, acc);
        d = p1.z - t1.z; acc = fmaf(d, d, acc);
        d = p1.w - t1.w; acc = fmaf(d, d, acc);
    }
    // Tail (at most one vector per thread)
    if (i < n_vec4) {
        float4 p = __ldg(&pred[i]);
        float4 t = __ldg(&tgt[i]);
        float d;
        d = p.x - t.x; acc = fmaf(d, d, acc);
        d = p.y - t.y; acc = fmaf(d, d, acc);
        d = p.z - t.z; acc = fmaf(d, d, acc);
        d = p.w - t.w; acc = fmaf(d, d, acc);
    }

    // Warp reduce
    #pragma unroll
    for (int off = 16; off > 0; off >>= 1)
        acc += __shfl_xor_sync(0xFFFFFFFFu, acc, off);

    // Block reduce via shared
    __shared__ float warp_sums[BLOCK_THREADS / 32];
    __shared__ bool  is_last;
    const int lane = tid & 31;
    const int wid  = tid >> 5;
    if (lane == 0) warp_sums[wid] = acc;
    __syncthreads();

    if (tid == 0) {
        float v = 0.0f;
        #pragma unroll
        for (int w = 0; w < BLOCK_THREADS / 32; w++)
            v += warp_sums[w];

        // Pre-scale so the final value needs no further math.
        atomicAdd(&g_accum, v * inv_norm);
        __threadfence();   // order the add before the arrival increment
        // atomicInc wraps to 0 at NUM_BLOCKS-1 -> self-resets each launch,
        // keeping graph replays deterministic.
        unsigned int prev = atomicInc(&g_arrival, NUM_BLOCKS - 1);
        is_last = (prev == NUM_BLOCKS - 1);
    }
    __syncthreads();

    // Last block: publish result, reset accumulator for the next replay.
    if (is_last && tid == 0) {
        float total = atomicAdd(&g_accum, 0.0f);   // atomic read
        out[0] = total;                             // overwrite poisoned d_out
        __threadfence();
        atomicExch(&g_accum, 0.0f);                 // reset for next launch
    }
}

extern "C" void kernel_launch(void* const* d_in, const int* in_sizes, int n_in,
                              void* d_out, int out_size)
{
    const float* pred = (const float*)d_in[0];
    const float* tgt  = (const float*)d_in[1];
    float* out = (float*)d_out;

    const long long total = (long long)in_sizes[0];   // B * S * 2 = 16,769,024
    const int n_vec4 = (int)(total / 4);              // 4,192,256
    // normalizer: S * B = total / 2
    const float inv_norm = 2.0f / (float)total;

    mse_fused_kernel<<<NUM_BLOCKS, BLOCK_THREADS>>>(
        (const float4*)pred, (const float4*)tgt, out, n_vec4, inv_norm);
}